// round 2
// baseline (speedup 1.0000x reference)
#include <cuda_runtime.h>
#include <cstdint>

#define BDIM 8
#define TDIM 8192
#define KDIM 64
#define DDIM 128
#define SEGL 32                      // segment length (timesteps)
#define NSEG (BDIM * TDIM / SEGL)    // 2048 segments total

typedef unsigned long long ull;

// ---------------- scratch (device globals; no allocation) ----------------
__device__ float  g_u[BDIM * TDIM * KDIM];        // raw x @ W^T
__device__ float4 g_segA[NSEG * KDIM];            // (Ar, Ai, BuR, BuI) per segment
__device__ float2 g_segS[NSEG * KDIM];            // (Sr, Si) suffix-A sums (bias path)
__device__ float2 g_hstart[NSEG * KDIM];          // h at segment start
__device__ float  g_inv_sigma;

// ---------------- packed f32x2 helpers ----------------
__device__ __forceinline__ void ffma2(ull& d, ull a, ull b) {
    asm("fma.rn.f32x2 %0, %1, %2, %0;" : "+l"(d) : "l"(a), "l"(b));
}
__device__ __forceinline__ ull dup2(float x) {
    ull r;
    asm("mov.b64 %0, {%1, %1};" : "=l"(r) : "f"(x));
    return r;
}

// =========================================================================
// Kernel 1: GEMM (register-tiled, FFMA2) + per-segment aggregates + sigma.
// Grid: 256 work blocks + 1 sigma block; 256 threads.
// Each work block: 256 consecutive bt-rows = 8 segments of 32.
// =========================================================================
__global__ __launch_bounds__(256, 2) void gemm_agg_kernel(
    const float* __restrict__ x,    const float* __restrict__ W,
    const float* __restrict__ dt,   const float* __restrict__ amod,
    const float* __restrict__ omod, const float* __restrict__ tmod,
    const float* __restrict__ srr,  const float* __restrict__ sim,
    const float* __restrict__ traw, const float* __restrict__ bias)
{
    __shared__ float pool[10784];   // ws[128*68] + xs[8*260]; sigma aliases front
    const int tid = threadIdx.x;

    if (blockIdx.x == 256) {
        // ---------------- sigma block: power iteration on W W^T -----------
        float* Ms = pool;            // [64][65]
        float* v0 = pool + 4224;
        float* v1 = pool + 4288;
        for (int e = tid; e < 4096; e += 256) {
            int r = e >> 6, cc = e & 63;
            const float4* a = (const float4*)(W + r  * DDIM);
            const float4* b = (const float4*)(W + cc * DDIM);
            float s = 0.f;
            #pragma unroll
            for (int d = 0; d < 32; d++) {
                float4 av = a[d], bv = b[d];
                s += av.x*bv.x + av.y*bv.y + av.z*bv.z + av.w*bv.w;
            }
            Ms[r*65 + cc] = s;
        }
        if (tid < 64) v0[tid] = 1.0f;
        __syncthreads();

        const int r = tid >> 2, part = tid & 3;
        float* va = v0; float* vb = v1;
        for (int it = 0; it < 256; it++) {
            float s = 0.f;
            #pragma unroll
            for (int j = 0; j < 16; j++)
                s += Ms[r*65 + part*16 + j] * va[part*16 + j];
            s += __shfl_xor_sync(0xffffffffu, s, 1);
            s += __shfl_xor_sync(0xffffffffu, s, 2);
            if (part == 0) vb[r] = ((it & 31) == 31) ? s * 1e-14f : s;
            __syncthreads();
            float* t = va; va = vb; vb = t;
        }
        {
            float s = 0.f;
            #pragma unroll
            for (int j = 0; j < 16; j++)
                s += Ms[r*65 + part*16 + j] * va[part*16 + j];
            s += __shfl_xor_sync(0xffffffffu, s, 1);
            s += __shfl_xor_sync(0xffffffffu, s, 2);
            if (part == 0) vb[r] = s;
        }
        __syncthreads();
        if (tid == 0) {
            float num = 0.f, den = 0.f;
            for (int j = 0; j < 64; j++) { num += va[j]*vb[j]; den += va[j]*va[j]; }
            g_inv_sigma = 1.0f / sqrtf(num / den);
        }
        return;
    }

    // ---------------- GEMM: 256 rows/block, 8M x 8N per thread ------------
    float* ws = pool;           // W^T: [128 d][68 pad], ws[d][n] = W[n][d]
    float* xs = pool + 8704;    // x chunk transposed: [8 kk][260 pad]

    for (int e = tid; e < KDIM * DDIM; e += 256) {
        int n = e >> 7, d = e & 127;
        ws[d*68 + n] = W[e];
    }

    const int tx = tid & 7;      // n group: n = tx*8 .. tx*8+7
    const int ty = tid >> 3;     // m group: m = ty + 32*i
    const int row0 = blockIdx.x * 256;
    const float* xb = x + (size_t)row0 * DDIM;

    ull acc[8][4];
    #pragma unroll
    for (int i = 0; i < 8; i++)
        #pragma unroll
        for (int j = 0; j < 4; j++) acc[i][j] = 0ull;

    for (int ch = 0; ch < 16; ch++) {
        __syncthreads();
        float4 v0 = *(const float4*)(xb + (size_t)tid * DDIM + ch * 8);
        float4 v1 = *(const float4*)(xb + (size_t)tid * DDIM + ch * 8 + 4);
        xs[0*260 + tid] = v0.x; xs[1*260 + tid] = v0.y;
        xs[2*260 + tid] = v0.z; xs[3*260 + tid] = v0.w;
        xs[4*260 + tid] = v1.x; xs[5*260 + tid] = v1.y;
        xs[6*260 + tid] = v1.z; xs[7*260 + tid] = v1.w;
        __syncthreads();
        #pragma unroll
        for (int kk = 0; kk < 8; kk++) {
            const float* xrow = &xs[kk*260 + ty];
            ull x2[8];
            #pragma unroll
            for (int i = 0; i < 8; i++) x2[i] = dup2(xrow[32*i]);
            const ull* wrow = (const ull*)&ws[(ch*8 + kk)*68 + tx*8];
            ull w0 = wrow[0], w1 = wrow[1], w2 = wrow[2], w3 = wrow[3];
            #pragma unroll
            for (int i = 0; i < 8; i++) {
                ffma2(acc[i][0], x2[i], w0);
                ffma2(acc[i][1], x2[i], w1);
                ffma2(acc[i][2], x2[i], w2);
                ffma2(acc[i][3], x2[i], w3);
            }
        }
    }
    #pragma unroll
    for (int i = 0; i < 8; i++) {
        int row = row0 + ty + 32*i;
        ull* dst = (ull*)&g_u[(size_t)row * KDIM + tx*8];
        *(ulonglong2*)&dst[0] = make_ulonglong2(acc[i][0], acc[i][1]);
        *(ulonglong2*)&dst[2] = make_ulonglong2(acc[i][2], acc[i][3]);
    }

    __syncthreads();   // g_u of this block's rows visible block-wide

    // ---------------- per-segment aggregates (sigma-independent form) ----
    const int k   = tid & 63;
    const int grp = tid >> 6;     // 0..3, handles segments grp and grp+4

    float tr  = traw[0];
    float tau = ((tr > 20.f) ? tr : log1pf(expf(tr))) + 1e-3f;
    float sr  = srr[k];
    float sp  = (sr > 20.f) ? sr : log1pf(expf(sr));
    float alpha0 = (sp + 1e-6f) * tau;
    float omega0 = sim[k] * tau;

    #pragma unroll
    for (int ss = 0; ss < 2; ss++) {
        int s  = grp + ss*4;
        int t0 = row0 + s*SEGL;              // global bt
        float Ar = 1.f, Ai = 0.f, Br = 0.f, Bi = 0.f, Sr = 0.f, Si = 0.f;
        for (int i = 0; i < SEGL; i++) {
            int bt = t0 + i;
            size_t idx = (size_t)bt * KDIM + k;
            float amv = amod[idx], omv = omod[idx];
            float scale = __expf(tmod[bt]);
            float dtv   = dt[bt];
            float alpha = alpha0 * __expf(amv) * scale;
            float omega = omega0 * __expf(omv) * scale;
            float rho   = __expf(-alpha * dtv);
            float sn, cs; __sincosf(omega * dtv, &sn, &cs);
            float car = rho * cs, cai = rho * sn;
            float uv  = g_u[idx];            // raw u' (sigma folded later)
            float nbr = car*Br - cai*Bi + uv;
            float nbi = car*Bi + cai*Br;
            Br = nbr; Bi = nbi;
            float nsr = car*Sr - cai*Si + 1.f;
            float nsi = car*Si + cai*Sr;
            Sr = nsr; Si = nsi;
            float nar = car*Ar - cai*Ai;
            float nai = car*Ai + cai*Ar;
            Ar = nar; Ai = nai;
        }
        int seg = (t0 >> 5);
        g_segA[(size_t)seg * KDIM + k] = make_float4(Ar, Ai, Br, Bi);
        g_segS[(size_t)seg * KDIM + k] = make_float2(Sr, Si);
    }
}

// =========================================================================
// Kernel 2: scan the 256 segment aggregates per (batch, k); emit h_start.
// Grid: 8 blocks (one per batch), 256 threads = 64 k x 4 groups of 64 segs.
// =========================================================================
__global__ __launch_bounds__(256) void seg_scan_kernel(
    const float* __restrict__ bias)
{
    __shared__ float4 sAgg[4][KDIM];
    __shared__ float4 sPre[4][KDIM];

    const int tid = threadIdx.x;
    const int k   = tid & 63;
    const int grp = tid >> 6;
    const int b   = blockIdx.x;
    const float invsig = g_inv_sigma;
    const float bk = bias[k];

    const size_t base = ((size_t)b * 256 + grp * 64) * KDIM + k;

    // phase 1: combine own 64 segments (collapse Bu,S -> B with sigma/bias)
    float Ar = 1.f, Ai = 0.f, Br = 0.f, Bi = 0.f;
    for (int s = 0; s < 64; s++) {
        float4 v = g_segA[base + (size_t)s * KDIM];
        float2 w = g_segS[base + (size_t)s * KDIM];
        float vBr = invsig * v.z + bk * w.x;
        float vBi = invsig * v.w + bk * w.y;
        float nAr = v.x*Ar - v.y*Ai;
        float nAi = v.x*Ai + v.y*Ar;
        float nBr = v.x*Br - v.y*Bi + vBr;
        float nBi = v.x*Bi + v.y*Br + vBi;
        Ar = nAr; Ai = nAi; Br = nBr; Bi = nBi;
    }
    sAgg[grp][k] = make_float4(Ar, Ai, Br, Bi);
    __syncthreads();

    // phase 2: exclusive scan over the 4 groups (threads 0..63)
    if (tid < 64) {
        float EAr = 1.f, EAi = 0.f, EBr = 0.f, EBi = 0.f;
        #pragma unroll
        for (int g = 0; g < 4; g++) {
            sPre[g][k] = make_float4(EAr, EAi, EBr, EBi);
            float4 v = sAgg[g][k];
            float nAr = v.x*EAr - v.y*EAi;
            float nAi = v.x*EAi + v.y*EAr;
            float nBr = v.x*EBr - v.y*EBi + v.z;
            float nBi = v.x*EBi + v.y*EBr + v.w;
            EAr = nAr; EAi = nAi; EBr = nBr; EBi = nBi;
        }
    }
    __syncthreads();

    // phase 3: re-walk segments, emit h at each segment start
    float4 E = sPre[grp][k];
    float EAr = E.x, EAi = E.y, EBr = E.z, EBi = E.w;
    for (int s = 0; s < 64; s++) {
        g_hstart[base + (size_t)s * KDIM] = make_float2(EBr, EBi);  // h0 = 0
        float4 v = g_segA[base + (size_t)s * KDIM];
        float2 w = g_segS[base + (size_t)s * KDIM];
        float vBr = invsig * v.z + bk * w.x;
        float vBi = invsig * v.w + bk * w.y;
        float nAr = v.x*EAr - v.y*EAi;
        float nAi = v.x*EAi + v.y*EAr;
        float nBr = v.x*EBr - v.y*EBi + vBr;
        float nBi = v.x*EBi + v.y*EBr + vBi;
        EAr = nAr; EAi = nAi; EBr = nBr; EBi = nBi;
    }
}

// =========================================================================
// Kernel 3: apply pass. Thread = (segment, k). No barriers, no smem.
// Grid: 512 blocks x 256 threads (4 segments per block).
// =========================================================================
__global__ __launch_bounds__(256) void apply_kernel(
    const float* __restrict__ dt,   const float* __restrict__ amod,
    const float* __restrict__ omod, const float* __restrict__ tmod,
    const float* __restrict__ srr,  const float* __restrict__ sim,
    const float* __restrict__ traw, const float* __restrict__ bias,
    float* __restrict__ out)
{
    const int tid = threadIdx.x;
    const int k   = tid & 63;
    const int seg = blockIdx.x * 4 + (tid >> 6);
    const int t0  = seg * SEGL;                  // global bt

    float tr  = traw[0];
    float tau = ((tr > 20.f) ? tr : log1pf(expf(tr))) + 1e-3f;
    float sr  = srr[k];
    float sp  = (sr > 20.f) ? sr : log1pf(expf(sr));
    float alpha0 = (sp + 1e-6f) * tau;
    float omega0 = sim[k] * tau;
    float bk     = bias[k];
    float invsig = g_inv_sigma;

    float2 h = g_hstart[(size_t)seg * KDIM + k];
    float hr = h.x, hi = h.y;

    #pragma unroll 8
    for (int i = 0; i < SEGL; i++) {
        int bt = t0 + i;
        size_t idx = (size_t)bt * KDIM + k;
        float amv = amod[idx], omv = omod[idx];
        float scale = __expf(tmod[bt]);
        float dtv   = dt[bt];
        float alpha = alpha0 * __expf(amv) * scale;
        float omega = omega0 * __expf(omv) * scale;
        float rho   = __expf(-alpha * dtv);
        float sn, cs; __sincosf(omega * dtv, &sn, &cs);
        float car = rho * cs, cai = rho * sn;
        float uv  = g_u[idx] * invsig + bk;
        float nr = car*hr - cai*hi + uv;
        float ni = car*hi + cai*hr;
        hr = nr; hi = ni;
        size_t ob = (size_t)bt * (2 * KDIM);
        out[ob + k]        = hr;   // C
        out[ob + KDIM + k] = hi;   // S
    }
}

// =========================================================================
extern "C" void kernel_launch(void* const* d_in, const int* in_sizes, int n_in,
                              void* d_out, int out_size)
{
    (void)in_sizes; (void)n_in; (void)out_size;
    const float* x    = (const float*)d_in[0];
    const float* dt   = (const float*)d_in[1];
    const float* amod = (const float*)d_in[2];
    const float* omod = (const float*)d_in[3];
    const float* tmod = (const float*)d_in[4];
    const float* srr  = (const float*)d_in[5];
    const float* sim  = (const float*)d_in[6];
    const float* traw = (const float*)d_in[7];
    const float* W    = (const float*)d_in[8];
    const float* bias = (const float*)d_in[9];
    float* out = (float*)d_out;

    gemm_agg_kernel<<<257, 256>>>(x, W, dt, amod, omod, tmod, srr, sim, traw, bias);
    seg_scan_kernel<<<8, 256>>>(bias);
    apply_kernel<<<NSEG / 4, 256>>>(dt, amod, omod, tmod, srr, sim, traw, bias, out);
}

// round 9
// speedup vs baseline: 1.2095x; 1.2095x over previous
#include <cuda_runtime.h>
#include <cuda_bf16.h>
#include <mma.h>
#include <cstdint>

using namespace nvcuda;

#define BDIM 8
#define TDIM 8192
#define KDIM 64
#define DDIM 128
#define SEGL 32
#define NSEG (BDIM * TDIM / SEGL)    // 2048
#define ROWS_PER_BLK 64
#define NBLK (BDIM * TDIM / ROWS_PER_BLK)   // 1024

// ---------------- scratch (device globals; no allocation) ----------------
__device__ float  g_u[BDIM * TDIM * KDIM];        // raw x @ W^T
__device__ float4 g_segA[NSEG * KDIM];            // (Ar, Ai, BuR, BuI)
__device__ float2 g_segS[NSEG * KDIM];            // (Sr, Si) bias path
__device__ float2 g_hstart[NSEG * KDIM];          // h at segment start
__device__ float  g_inv_sigma;

// smem: A_hi, A_lo: [64][136] bf16; B_hi, B_lo: [64][136] bf16
#define LDS_PAD 136
#define TILE_HALF (ROWS_PER_BLK * LDS_PAD)        // elements per half
#define SMEM_GEMM (4 * TILE_HALF * 2)             // bytes = 69632

// =========================================================================
// Kernel 1: u = x @ W^T via wmma bf16 split (hi*hi + lo*hi + hi*lo) + sigma
// Grid: 1024 GEMM blocks (64 rows each) + 1 sigma block; 128 threads.
// =========================================================================
__global__ __launch_bounds__(128)
void gemm_wmma_kernel(const float* __restrict__ x, const float* __restrict__ W)
{
    extern __shared__ __align__(16) char dsm[];
    const int tid = threadIdx.x;

    if (blockIdx.x == NBLK) {
        // -------- sigma block: power iteration on W W^T (64x64) ----------
        float* Ms = (float*)dsm;          // [64][65]
        float* v0 = Ms + 4160;
        float* v1 = v0 + 64;
        for (int e = tid; e < 4096; e += 128) {
            int r = e >> 6, c = e & 63;
            const float4* a = (const float4*)(W + r * DDIM);
            const float4* b = (const float4*)(W + c * DDIM);
            float s = 0.f;
            #pragma unroll
            for (int d = 0; d < 32; d++) {
                float4 av = a[d], bv = b[d];
                s += av.x*bv.x + av.y*bv.y + av.z*bv.z + av.w*bv.w;
            }
            Ms[r*65 + c] = s;
        }
        if (tid < 64) v0[tid] = 1.0f;
        __syncthreads();
        const int r = tid >> 1, part = tid & 1;
        float* va = v0; float* vb = v1;
        for (int it = 0; it < 256; it++) {
            float s = 0.f;
            #pragma unroll
            for (int j = 0; j < 32; j++)
                s += Ms[r*65 + part*32 + j] * va[part*32 + j];
            s += __shfl_xor_sync(0xffffffffu, s, 1);
            if (part == 0) vb[r] = ((it & 31) == 31) ? s * 1e-14f : s;
            __syncthreads();
            float* t = va; va = vb; vb = t;
        }
        {   // Rayleigh quotient
            float s = 0.f;
            #pragma unroll
            for (int j = 0; j < 32; j++)
                s += Ms[r*65 + part*32 + j] * va[part*32 + j];
            s += __shfl_xor_sync(0xffffffffu, s, 1);
            if (part == 0) vb[r] = s;
        }
        __syncthreads();
        if (tid == 0) {
            float num = 0.f, den = 0.f;
            for (int j = 0; j < 64; j++) { num += va[j]*vb[j]; den += va[j]*va[j]; }
            g_inv_sigma = 1.0f / sqrtf(num / den);
        }
        return;
    }

    // ---------------- GEMM block -----------------------------------------
    __nv_bfloat16* sAhi = (__nv_bfloat16*)dsm;
    __nv_bfloat16* sAlo = sAhi + TILE_HALF;
    __nv_bfloat16* sBhi = sAlo + TILE_HALF;
    __nv_bfloat16* sBlo = sBhi + TILE_HALF;

    const int row0 = blockIdx.x * ROWS_PER_BLK;

    // stage x tile [64 rows][128 d] split hi/lo  (2048 float4, 16/thread)
    {
        const float4* xb = (const float4*)(x + (size_t)row0 * DDIM);
        #pragma unroll
        for (int i = 0; i < 16; i++) {
            int e = tid + 128 * i;             // float4 index
            int r = e >> 5, c4 = e & 31;       // 32 float4 per row
            float4 v = xb[e];
            __nv_bfloat16* dh = &sAhi[r * LDS_PAD + c4 * 4];
            __nv_bfloat16* dl = &sAlo[r * LDS_PAD + c4 * 4];
            float vv[4] = {v.x, v.y, v.z, v.w};
            #pragma unroll
            for (int q = 0; q < 4; q++) {
                __nv_bfloat16 h = __float2bfloat16(vv[q]);
                dh[q] = h;
                dl[q] = __float2bfloat16(vv[q] - __bfloat162float(h));
            }
        }
        // stage W [64 n][128 d] split hi/lo (2048 float4, 16/thread)
        const float4* wb = (const float4*)W;
        #pragma unroll
        for (int i = 0; i < 16; i++) {
            int e = tid + 128 * i;
            int r = e >> 5, c4 = e & 31;
            float4 v = wb[e];
            __nv_bfloat16* dh = &sBhi[r * LDS_PAD + c4 * 4];
            __nv_bfloat16* dl = &sBlo[r * LDS_PAD + c4 * 4];
            float vv[4] = {v.x, v.y, v.z, v.w};
            #pragma unroll
            for (int q = 0; q < 4; q++) {
                __nv_bfloat16 h = __float2bfloat16(vv[q]);
                dh[q] = h;
                dl[q] = __float2bfloat16(vv[q] - __bfloat162float(h));
            }
        }
    }
    __syncthreads();

    // each warp: 16 rows x 64 cols = 4 accum tiles of 16x16
    const int w = tid >> 5;
    wmma::fragment<wmma::accumulator, 16, 16, 16, float> fc[4];
    #pragma unroll
    for (int nt = 0; nt < 4; nt++) wmma::fill_fragment(fc[nt], 0.0f);

    wmma::fragment<wmma::matrix_a, 16, 16, 16, __nv_bfloat16, wmma::row_major> fa;
    wmma::fragment<wmma::matrix_b, 16, 16, 16, __nv_bfloat16, wmma::col_major> fb;

    const __nv_bfloat16* aSrc[3] = { sAhi, sAlo, sAhi };
    const __nv_bfloat16* bSrc[3] = { sBhi, sBhi, sBlo };

    #pragma unroll
    for (int p = 0; p < 3; p++) {
        const __nv_bfloat16* As = aSrc[p] + (w * 16) * LDS_PAD;
        const __nv_bfloat16* Bs = bSrc[p];
        #pragma unroll
        for (int kk = 0; kk < 8; kk++) {
            wmma::load_matrix_sync(fa, As + kk * 16, LDS_PAD);
            #pragma unroll
            for (int nt = 0; nt < 4; nt++) {
                wmma::load_matrix_sync(fb, Bs + (nt * 16) * LDS_PAD + kk * 16, LDS_PAD);
                wmma::mma_sync(fc[nt], fa, fb, fc[nt]);
            }
        }
    }

    float* outp = &g_u[(size_t)(row0 + w * 16) * KDIM];
    #pragma unroll
    for (int nt = 0; nt < 4; nt++)
        wmma::store_matrix_sync(outp + nt * 16, fc[nt], KDIM, wmma::mem_row_major);
}

// =========================================================================
// Kernel 2: per-segment aggregates (sigma-independent). Grid 512 x 256.
// =========================================================================
__global__ __launch_bounds__(256) void aggregate_kernel(
    const float* __restrict__ dt,   const float* __restrict__ amod,
    const float* __restrict__ omod, const float* __restrict__ tmod,
    const float* __restrict__ srr,  const float* __restrict__ sim,
    const float* __restrict__ traw)
{
    const int tid = threadIdx.x;
    const int k   = tid & 63;
    const int seg = blockIdx.x * 4 + (tid >> 6);
    const int t0  = seg * SEGL;

    float tr  = traw[0];
    float tau = ((tr > 20.f) ? tr : log1pf(expf(tr))) + 1e-3f;
    float sr  = srr[k];
    float sp  = (sr > 20.f) ? sr : log1pf(expf(sr));
    float alpha0 = (sp + 1e-6f) * tau;
    float omega0 = sim[k] * tau;

    float Ar = 1.f, Ai = 0.f, Br = 0.f, Bi = 0.f, Sr = 0.f, Si = 0.f;
    #pragma unroll 4
    for (int i = 0; i < SEGL; i++) {
        int bt = t0 + i;
        size_t idx = (size_t)bt * KDIM + k;
        float amv = amod[idx], omv = omod[idx];
        float scale = __expf(tmod[bt]);
        float dtv   = dt[bt];
        float alpha = alpha0 * __expf(amv) * scale;
        float omega = omega0 * __expf(omv) * scale;
        float rho   = __expf(-alpha * dtv);
        float sn, cs; __sincosf(omega * dtv, &sn, &cs);
        float car = rho * cs, cai = rho * sn;
        float uv  = g_u[idx];
        float nbr = car*Br - cai*Bi + uv;
        float nbi = car*Bi + cai*Br;
        Br = nbr; Bi = nbi;
        float nsr = car*Sr - cai*Si + 1.f;
        float nsi = car*Si + cai*Sr;
        Sr = nsr; Si = nsi;
        float nar = car*Ar - cai*Ai;
        float nai = car*Ai + cai*Ar;
        Ar = nar; Ai = nai;
    }
    g_segA[(size_t)seg * KDIM + k] = make_float4(Ar, Ai, Br, Bi);
    g_segS[(size_t)seg * KDIM + k] = make_float2(Sr, Si);
}

// =========================================================================
// Kernel 3: scan 256 segment aggregates per (batch,k); emit h_start.
// Grid 8 x 512: 64 k x 8 groups of 32 segments.
// =========================================================================
__global__ __launch_bounds__(512) void seg_scan_kernel(const float* __restrict__ bias)
{
    __shared__ float4 sAgg[8][KDIM];
    __shared__ float4 sPre[8][KDIM];

    const int tid = threadIdx.x;
    const int k   = tid & 63;
    const int grp = tid >> 6;
    const int b   = blockIdx.x;
    const float invsig = g_inv_sigma;
    const float bk = bias[k];

    const size_t base = ((size_t)b * 256 + grp * 32) * KDIM + k;

    float Ar = 1.f, Ai = 0.f, Br = 0.f, Bi = 0.f;
    #pragma unroll 4
    for (int s = 0; s < 32; s++) {
        float4 v = g_segA[base + (size_t)s * KDIM];
        float2 w = g_segS[base + (size_t)s * KDIM];
        float vBr = invsig * v.z + bk * w.x;
        float vBi = invsig * v.w + bk * w.y;
        float nAr = v.x*Ar - v.y*Ai;
        float nAi = v.x*Ai + v.y*Ar;
        float nBr = v.x*Br - v.y*Bi + vBr;
        float nBi = v.x*Bi + v.y*Br + vBi;
        Ar = nAr; Ai = nAi; Br = nBr; Bi = nBi;
    }
    sAgg[grp][k] = make_float4(Ar, Ai, Br, Bi);
    __syncthreads();

    if (tid < 64) {
        float EAr = 1.f, EAi = 0.f, EBr = 0.f, EBi = 0.f;
        #pragma unroll
        for (int g = 0; g < 8; g++) {
            sPre[g][k] = make_float4(EAr, EAi, EBr, EBi);
            float4 v = sAgg[g][k];
            float nAr = v.x*EAr - v.y*EAi;
            float nAi = v.x*EAi + v.y*EAr;
            float nBr = v.x*EBr - v.y*EBi + v.z;
            float nBi = v.x*EBi + v.y*EBr + v.w;
            EAr = nAr; EAi = nAi; EBr = nBr; EBi = nBi;
        }
    }
    __syncthreads();

    float4 E = sPre[grp][k];
    float EAr = E.x, EAi = E.y, EBr = E.z, EBi = E.w;
    #pragma unroll 4
    for (int s = 0; s < 32; s++) {
        g_hstart[base + (size_t)s * KDIM] = make_float2(EBr, EBi);
        float4 v = g_segA[base + (size_t)s * KDIM];
        float2 w = g_segS[base + (size_t)s * KDIM];
        float vBr = invsig * v.z + bk * w.x;
        float vBi = invsig * v.w + bk * w.y;
        float nAr = v.x*EAr - v.y*EAi;
        float nAi = v.x*EAi + v.y*EAr;
        float nBr = v.x*EBr - v.y*EBi + vBr;
        float nBi = v.x*EBi + v.y*EBr + vBi;
        EAr = nAr; EAi = nAi; EBr = nBr; EBi = nBi;
    }
}

// =========================================================================
// Kernel 4: apply pass. Thread = (segment, k). Grid 512 x 256.
// =========================================================================
__global__ __launch_bounds__(256) void apply_kernel(
    const float* __restrict__ dt,   const float* __restrict__ amod,
    const float* __restrict__ omod, const float* __restrict__ tmod,
    const float* __restrict__ srr,  const float* __restrict__ sim,
    const float* __restrict__ traw, const float* __restrict__ bias,
    float* __restrict__ out)
{
    const int tid = threadIdx.x;
    const int k   = tid & 63;
    const int seg = blockIdx.x * 4 + (tid >> 6);
    const int t0  = seg * SEGL;

    float tr  = traw[0];
    float tau = ((tr > 20.f) ? tr : log1pf(expf(tr))) + 1e-3f;
    float sr  = srr[k];
    float sp  = (sr > 20.f) ? sr : log1pf(expf(sr));
    float alpha0 = (sp + 1e-6f) * tau;
    float omega0 = sim[k] * tau;
    float bk     = bias[k];
    float invsig = g_inv_sigma;

    float2 h = g_hstart[(size_t)seg * KDIM + k];
    float hr = h.x, hi = h.y;

    #pragma unroll 4
    for (int i = 0; i < SEGL; i++) {
        int bt = t0 + i;
        size_t idx = (size_t)bt * KDIM + k;
        float amv = amod[idx], omv = omod[idx];
        float scale = __expf(tmod[bt]);
        float dtv   = dt[bt];
        float alpha = alpha0 * __expf(amv) * scale;
        float omega = omega0 * __expf(omv) * scale;
        float rho   = __expf(-alpha * dtv);
        float sn, cs; __sincosf(omega * dtv, &sn, &cs);
        float car = rho * cs, cai = rho * sn;
        float uv  = g_u[idx] * invsig + bk;
        float nr = car*hr - cai*hi + uv;
        float ni = car*hi + cai*hr;
        hr = nr; hi = ni;
        size_t ob = (size_t)bt * (2 * KDIM);
        out[ob + k]        = hr;   // C
        out[ob + KDIM + k] = hi;   // S
    }
}

// =========================================================================
extern "C" void kernel_launch(void* const* d_in, const int* in_sizes, int n_in,
                              void* d_out, int out_size)
{
    (void)in_sizes; (void)n_in; (void)out_size;
    const float* x    = (const float*)d_in[0];
    const float* dt   = (const float*)d_in[1];
    const float* amod = (const float*)d_in[2];
    const float* omod = (const float*)d_in[3];
    const float* tmod = (const float*)d_in[4];
    const float* srr  = (const float*)d_in[5];
    const float* sim  = (const float*)d_in[6];
    const float* traw = (const float*)d_in[7];
    const float* W    = (const float*)d_in[8];
    const float* bias = (const float*)d_in[9];
    float* out = (float*)d_out;

    cudaFuncSetAttribute(gemm_wmma_kernel,
                         cudaFuncAttributeMaxDynamicSharedMemorySize, SMEM_GEMM);

    gemm_wmma_kernel<<<NBLK + 1, 128, SMEM_GEMM>>>(x, W);
    aggregate_kernel<<<512, 256>>>(dt, amod, omod, tmod, srr, sim, traw);
    seg_scan_kernel<<<8, 512>>>(bias);
    apply_kernel<<<512, 256>>>(dt, amod, omod, tmod, srr, sim, traw, bias, out);
}

// round 10
// speedup vs baseline: 1.2434x; 1.0280x over previous
#include <cuda_runtime.h>
#include <cuda_bf16.h>
#include <mma.h>
#include <cstdint>

using namespace nvcuda;

#define BDIM 8
#define TDIM 8192
#define KDIM 64
#define DDIM 128
#define SEGL 16
#define NSEG (BDIM * TDIM / SEGL)           // 4096
#define ROWS_PER_BLK 128
#define NBLK (BDIM * TDIM / ROWS_PER_BLK)   // 512

// ---------------- scratch (device globals; no allocation) ----------------
__device__ float  g_u[BDIM * TDIM * KDIM];        // raw x @ W^T
__device__ float4 g_segA[NSEG * KDIM];            // (Ar, Ai, BuR, BuI)
__device__ float2 g_segS[NSEG * KDIM];            // (Sr, Si) bias path
__device__ float2 g_hstart[NSEG * KDIM];          // h at segment start
__device__ float  g_inv_sigma;

// smem: A_hi/A_lo [128][136] bf16, B_hi/B_lo [64][136] bf16
#define LDS_PAD 136
#define A_HALF (ROWS_PER_BLK * LDS_PAD)
#define B_HALF (KDIM * LDS_PAD)
#define SMEM_GEMM ((2 * A_HALF + 2 * B_HALF) * 2)   // 104448 bytes

// =========================================================================
// Kernel 1: u = x@W^T (wmma bf16 split: hi*hi + lo*hi + hi*lo) + fused
// per-segment aggregates + sigma block.
// Grid: 512 GEMM blocks (128 rows = 8 segments each) + 1 sigma block; 256 thr.
// =========================================================================
__global__ __launch_bounds__(256)
void gemm_agg_kernel(const float* __restrict__ x,    const float* __restrict__ W,
                     const float* __restrict__ dt,   const float* __restrict__ amod,
                     const float* __restrict__ omod, const float* __restrict__ tmod,
                     const float* __restrict__ srr,  const float* __restrict__ sim,
                     const float* __restrict__ traw)
{
    extern __shared__ __align__(16) char dsm[];
    const int tid = threadIdx.x;

    if (blockIdx.x == NBLK) {
        // -------- sigma block: power iteration on W W^T (64x64) ----------
        float* Ms = (float*)dsm;          // [64][65]
        float* v0 = Ms + 4160;
        float* v1 = v0 + 64;
        for (int e = tid; e < 4096; e += 256) {
            int r = e >> 6, c = e & 63;
            const float4* a = (const float4*)(W + r * DDIM);
            const float4* b = (const float4*)(W + c * DDIM);
            float s = 0.f;
            #pragma unroll
            for (int d = 0; d < 32; d++) {
                float4 av = a[d], bv = b[d];
                s += av.x*bv.x + av.y*bv.y + av.z*bv.z + av.w*bv.w;
            }
            Ms[r*65 + c] = s;
        }
        if (tid < 64) v0[tid] = 1.0f;
        __syncthreads();
        if (tid < 128) {
            const int r = tid >> 1, part = tid & 1;
            float* va = v0; float* vb = v1;
            for (int it = 0; it < 256; it++) {
                float s = 0.f;
                #pragma unroll
                for (int j = 0; j < 32; j++)
                    s += Ms[r*65 + part*32 + j] * va[part*32 + j];
                s += __shfl_xor_sync(0xffffffffu, s, 1);
                if (part == 0) vb[r] = ((it & 31) == 31) ? s * 1e-14f : s;
                __syncthreads();
                float* t = va; va = vb; vb = t;
            }
            {   // Rayleigh quotient
                float s = 0.f;
                #pragma unroll
                for (int j = 0; j < 32; j++)
                    s += Ms[r*65 + part*32 + j] * va[part*32 + j];
                s += __shfl_xor_sync(0xffffffffu, s, 1);
                if (part == 0) vb[r] = s;
            }
            __syncthreads();
            if (tid == 0) {
                float num = 0.f, den = 0.f;
                for (int j = 0; j < 64; j++) { num += va[j]*vb[j]; den += va[j]*va[j]; }
                g_inv_sigma = 1.0f / sqrtf(num / den);
            }
        }
        return;
    }

    // ---------------- GEMM ------------------------------------------------
    __nv_bfloat16* sAhi = (__nv_bfloat16*)dsm;
    __nv_bfloat16* sAlo = sAhi + A_HALF;
    __nv_bfloat16* sBhi = sAlo + A_HALF;
    __nv_bfloat16* sBlo = sBhi + B_HALF;

    const int row0 = blockIdx.x * ROWS_PER_BLK;

    {   // stage x tile [128 rows][128 d] split hi/lo : 4096 float4, 16/thread
        const float4* xb = (const float4*)(x + (size_t)row0 * DDIM);
        #pragma unroll
        for (int i = 0; i < 16; i++) {
            int e = tid + 256 * i;
            int r = e >> 5, c4 = e & 31;
            float4 v = xb[e];
            __nv_bfloat16* dh = &sAhi[r * LDS_PAD + c4 * 4];
            __nv_bfloat16* dl = &sAlo[r * LDS_PAD + c4 * 4];
            float vv[4] = {v.x, v.y, v.z, v.w};
            #pragma unroll
            for (int q = 0; q < 4; q++) {
                __nv_bfloat16 h = __float2bfloat16(vv[q]);
                dh[q] = h;
                dl[q] = __float2bfloat16(vv[q] - __bfloat162float(h));
            }
        }
        // stage W [64 n][128 d] split hi/lo : 2048 float4, 8/thread
        const float4* wb = (const float4*)W;
        #pragma unroll
        for (int i = 0; i < 8; i++) {
            int e = tid + 256 * i;
            int r = e >> 5, c4 = e & 31;
            float4 v = wb[e];
            __nv_bfloat16* dh = &sBhi[r * LDS_PAD + c4 * 4];
            __nv_bfloat16* dl = &sBlo[r * LDS_PAD + c4 * 4];
            float vv[4] = {v.x, v.y, v.z, v.w};
            #pragma unroll
            for (int q = 0; q < 4; q++) {
                __nv_bfloat16 h = __float2bfloat16(vv[q]);
                dh[q] = h;
                dl[q] = __float2bfloat16(vv[q] - __bfloat162float(h));
            }
        }
    }
    __syncthreads();

    // 8 warps: warp w covers rows w*16..w*16+15, all 64 cols (4 tiles)
    {
        const int w = tid >> 5;
        wmma::fragment<wmma::accumulator, 16, 16, 16, float> fc[4];
        #pragma unroll
        for (int nt = 0; nt < 4; nt++) wmma::fill_fragment(fc[nt], 0.0f);

        wmma::fragment<wmma::matrix_a, 16, 16, 16, __nv_bfloat16, wmma::row_major> fa;
        wmma::fragment<wmma::matrix_b, 16, 16, 16, __nv_bfloat16, wmma::col_major> fb;

        const __nv_bfloat16* aSrc[3] = { sAhi, sAlo, sAhi };
        const __nv_bfloat16* bSrc[3] = { sBhi, sBhi, sBlo };

        #pragma unroll
        for (int p = 0; p < 3; p++) {
            const __nv_bfloat16* As = aSrc[p] + (w * 16) * LDS_PAD;
            const __nv_bfloat16* Bs = bSrc[p];
            #pragma unroll
            for (int kk = 0; kk < 8; kk++) {
                wmma::load_matrix_sync(fa, As + kk * 16, LDS_PAD);
                #pragma unroll
                for (int nt = 0; nt < 4; nt++) {
                    wmma::load_matrix_sync(fb, Bs + (nt * 16) * LDS_PAD + kk * 16, LDS_PAD);
                    wmma::mma_sync(fc[nt], fa, fb, fc[nt]);
                }
            }
        }
        float* outp = &g_u[(size_t)(row0 + w * 16) * KDIM];
        #pragma unroll
        for (int nt = 0; nt < 4; nt++)
            wmma::store_matrix_sync(outp + nt * 16, fc[nt], KDIM, wmma::mem_row_major);
    }
    __syncthreads();   // own-block g_u writes now visible (same SM)

    // ---------------- fused per-segment aggregates ------------------------
    const int k   = tid & 63;
    const int grp = tid >> 6;       // 0..3; handles segments grp, grp+4

    float tr  = traw[0];
    float tau = ((tr > 20.f) ? tr : log1pf(expf(tr))) + 1e-3f;
    float sr  = srr[k];
    float sp  = (sr > 20.f) ? sr : log1pf(expf(sr));
    float alpha0 = (sp + 1e-6f) * tau;
    float omega0 = sim[k] * tau;

    #pragma unroll
    for (int ss = 0; ss < 2; ss++) {
        int s  = grp + ss * 4;
        int t0 = row0 + s * SEGL;
        float Ar = 1.f, Ai = 0.f, Br = 0.f, Bi = 0.f, Sr = 0.f, Si = 0.f;
        #pragma unroll 4
        for (int i = 0; i < SEGL; i++) {
            int bt = t0 + i;
            size_t idx = (size_t)bt * KDIM + k;
            float tv  = tmod[bt];
            float dtv = dt[bt];
            float alpha = alpha0 * __expf(amod[idx] + tv);
            float omega = omega0 * __expf(omod[idx] + tv);
            float rho   = __expf(-alpha * dtv);
            float sn, cs; __sincosf(omega * dtv, &sn, &cs);
            float car = rho * cs, cai = rho * sn;
            float uv  = g_u[idx];
            float nbr = car*Br - cai*Bi + uv;
            float nbi = car*Bi + cai*Br;
            Br = nbr; Bi = nbi;
            float nsr = car*Sr - cai*Si + 1.f;
            float nsi = car*Si + cai*Sr;
            Sr = nsr; Si = nsi;
            float nar = car*Ar - cai*Ai;
            float nai = car*Ai + cai*Ar;
            Ar = nar; Ai = nai;
        }
        int seg = t0 / SEGL;
        g_segA[(size_t)seg * KDIM + k] = make_float4(Ar, Ai, Br, Bi);
        g_segS[(size_t)seg * KDIM + k] = make_float2(Sr, Si);
    }
}

// =========================================================================
// Kernel 2: scan 512 segment aggregates per (batch,k); emit h_start.
// Grid 8 x 1024: 64 k x 16 groups of 32 segments.
// =========================================================================
__global__ __launch_bounds__(1024) void seg_scan_kernel(const float* __restrict__ bias)
{
    __shared__ float4 sAgg[16][KDIM];
    __shared__ float4 sPre[16][KDIM];

    const int tid = threadIdx.x;
    const int k   = tid & 63;
    const int grp = tid >> 6;       // 0..15
    const int b   = blockIdx.x;
    const float invsig = g_inv_sigma;
    const float bk = bias[k];

    const size_t base = ((size_t)b * 512 + grp * 32) * KDIM + k;

    float Ar = 1.f, Ai = 0.f, Br = 0.f, Bi = 0.f;
    #pragma unroll 4
    for (int s = 0; s < 32; s++) {
        float4 v = g_segA[base + (size_t)s * KDIM];
        float2 w = g_segS[base + (size_t)s * KDIM];
        float vBr = invsig * v.z + bk * w.x;
        float vBi = invsig * v.w + bk * w.y;
        float nAr = v.x*Ar - v.y*Ai;
        float nAi = v.x*Ai + v.y*Ar;
        float nBr = v.x*Br - v.y*Bi + vBr;
        float nBi = v.x*Bi + v.y*Br + vBi;
        Ar = nAr; Ai = nAi; Br = nBr; Bi = nBi;
    }
    sAgg[grp][k] = make_float4(Ar, Ai, Br, Bi);
    __syncthreads();

    if (tid < 64) {
        float EAr = 1.f, EAi = 0.f, EBr = 0.f, EBi = 0.f;
        #pragma unroll
        for (int g = 0; g < 16; g++) {
            sPre[g][k] = make_float4(EAr, EAi, EBr, EBi);
            float4 v = sAgg[g][k];
            float nAr = v.x*EAr - v.y*EAi;
            float nAi = v.x*EAi + v.y*EAr;
            float nBr = v.x*EBr - v.y*EBi + v.z;
            float nBi = v.x*EBi + v.y*EBr + v.w;
            EAr = nAr; EAi = nAi; EBr = nBr; EBi = nBi;
        }
    }
    __syncthreads();

    float4 E = sPre[grp][k];
    float EAr = E.x, EAi = E.y, EBr = E.z, EBi = E.w;
    #pragma unroll 4
    for (int s = 0; s < 32; s++) {
        g_hstart[base + (size_t)s * KDIM] = make_float2(EBr, EBi);
        float4 v = g_segA[base + (size_t)s * KDIM];
        float2 w = g_segS[base + (size_t)s * KDIM];
        float vBr = invsig * v.z + bk * w.x;
        float vBi = invsig * v.w + bk * w.y;
        float nAr = v.x*EAr - v.y*EAi;
        float nAi = v.x*EAi + v.y*EAr;
        float nBr = v.x*EBr - v.y*EBi + vBr;
        float nBi = v.x*EBi + v.y*EBr + vBi;
        EAr = nAr; EAi = nAi; EBr = nBr; EBi = nBi;
    }
}

// =========================================================================
// Kernel 3: apply pass. Thread = (segment, k). Grid 1024 x 256.
// =========================================================================
__global__ __launch_bounds__(256) void apply_kernel(
    const float* __restrict__ dt,   const float* __restrict__ amod,
    const float* __restrict__ omod, const float* __restrict__ tmod,
    const float* __restrict__ srr,  const float* __restrict__ sim,
    const float* __restrict__ traw, const float* __restrict__ bias,
    float* __restrict__ out)
{
    const int tid = threadIdx.x;
    const int k   = tid & 63;
    const int seg = blockIdx.x * 4 + (tid >> 6);
    const int t0  = seg * SEGL;

    float tr  = traw[0];
    float tau = ((tr > 20.f) ? tr : log1pf(expf(tr))) + 1e-3f;
    float sr  = srr[k];
    float sp  = (sr > 20.f) ? sr : log1pf(expf(sr));
    float alpha0 = (sp + 1e-6f) * tau;
    float omega0 = sim[k] * tau;
    float bk     = bias[k];
    float invsig = g_inv_sigma;

    float2 h = g_hstart[(size_t)seg * KDIM + k];
    float hr = h.x, hi = h.y;

    #pragma unroll 4
    for (int i = 0; i < SEGL; i++) {
        int bt = t0 + i;
        size_t idx = (size_t)bt * KDIM + k;
        float tv  = tmod[bt];
        float dtv = dt[bt];
        float alpha = alpha0 * __expf(amod[idx] + tv);
        float omega = omega0 * __expf(omod[idx] + tv);
        float rho   = __expf(-alpha * dtv);
        float sn, cs; __sincosf(omega * dtv, &sn, &cs);
        float car = rho * cs, cai = rho * sn;
        float uv  = g_u[idx] * invsig + bk;
        float nr = car*hr - cai*hi + uv;
        float ni = car*hi + cai*hr;
        hr = nr; hi = ni;
        size_t ob = (size_t)bt * (2 * KDIM);
        out[ob + k]        = hr;   // C
        out[ob + KDIM + k] = hi;   // S
    }
}

// =========================================================================
extern "C" void kernel_launch(void* const* d_in, const int* in_sizes, int n_in,
                              void* d_out, int out_size)
{
    (void)in_sizes; (void)n_in; (void)out_size;
    const float* x    = (const float*)d_in[0];
    const float* dt   = (const float*)d_in[1];
    const float* amod = (const float*)d_in[2];
    const float* omod = (const float*)d_in[3];
    const float* tmod = (const float*)d_in[4];
    const float* srr  = (const float*)d_in[5];
    const float* sim  = (const float*)d_in[6];
    const float* traw = (const float*)d_in[7];
    const float* W    = (const float*)d_in[8];
    const float* bias = (const float*)d_in[9];
    float* out = (float*)d_out;

    cudaFuncSetAttribute(gemm_agg_kernel,
                         cudaFuncAttributeMaxDynamicSharedMemorySize, SMEM_GEMM);

    gemm_agg_kernel<<<NBLK + 1, 256, SMEM_GEMM>>>(x, W, dt, amod, omod, tmod,
                                                  srr, sim, traw);
    seg_scan_kernel<<<8, 1024>>>(bias);
    apply_kernel<<<NSEG / 4, 256>>>(dt, amod, omod, tmod, srr, sim, traw, bias, out);
}

// round 12
// speedup vs baseline: 1.5623x; 1.2565x over previous
#include <cuda_runtime.h>
#include <cuda_bf16.h>
#include <mma.h>
#include <cstdint>

using namespace nvcuda;

#define BDIM 8
#define TDIM 8192
#define KDIM 64
#define DDIM 128
#define SEGL 16
#define NSEG (BDIM * TDIM / SEGL)           // 4096
#define GROWS 64
#define NGBLK (BDIM * TDIM / GROWS)         // 1024 gemm blocks

// ---------------- scratch (device globals; no allocation) ----------------
__device__ float  g_u[BDIM * TDIM * KDIM];        // raw x @ W^T
__device__ float4 g_segA[NSEG * KDIM];            // (Ar, Ai, BuR, BuI)
__device__ float2 g_segS[NSEG * KDIM];            // (Sr, Si) bias path
__device__ float2 g_hstart[NSEG * KDIM];          // h at segment start
__device__ float  g_inv_sigma;
__device__ __nv_bfloat16 g_Whi[KDIM * DDIM];      // W split hi
__device__ __nv_bfloat16 g_Wlo[KDIM * DDIM];      // W split lo

#define LDS_PAD 136                                // >= DDIM, mult of 8
#define TILE_HALF (GROWS * LDS_PAD)                // 8704 elements per half

// =========================================================================
// Kernel 0: split W -> bf16 hi/lo in global (one tiny block)
// =========================================================================
__global__ __launch_bounds__(128) void prep_kernel(const float* __restrict__ W)
{
    const int tid = threadIdx.x;
    #pragma unroll
    for (int i = 0; i < KDIM * DDIM / 128; i++) {
        int e = tid + 128 * i;
        float v = W[e];
        __nv_bfloat16 h = __float2bfloat16(v);
        g_Whi[e] = h;
        g_Wlo[e] = __float2bfloat16(v - __bfloat162float(h));
    }
}

// =========================================================================
// Kernel 1: u = x@W^T (wmma bf16 split hi*hi + lo*hi + hi*lo).
// A tile (x) hi/lo staged in smem; B fragments loaded DIRECTLY from global
// (g_Whi/g_Wlo, 32KB L1-resident). Block 0 = sigma power iteration.
// Grid: 1 + 1024 blocks; 128 threads (4 warps, 16 rows each).
// =========================================================================
__global__ __launch_bounds__(128)
void gemm_wmma_kernel(const float* __restrict__ x, const float* __restrict__ W)
{
    __shared__ __align__(16) __nv_bfloat16 sm[2 * TILE_HALF];   // 34816 B
    const int tid = threadIdx.x;

    if (blockIdx.x == 0) {
        // -------- sigma block: power iteration on W W^T (64x64) ----------
        float* Ms = (float*)sm;           // [64][65] = 16.6 KB
        float* v0 = Ms + 4160;
        float* v1 = v0 + 64;
        for (int e = tid; e < 4096; e += 128) {
            int r = e >> 6, c = e & 63;
            const float4* a = (const float4*)(W + r * DDIM);
            const float4* b = (const float4*)(W + c * DDIM);
            float s = 0.f;
            #pragma unroll
            for (int d = 0; d < 32; d++) {
                float4 av = a[d], bv = b[d];
                s += av.x*bv.x + av.y*bv.y + av.z*bv.z + av.w*bv.w;
            }
            Ms[r*65 + c] = s;
        }
        if (tid < 64) v0[tid] = 1.0f;
        __syncthreads();
        const int r = tid >> 1, part = tid & 1;
        float* va = v0; float* vb = v1;
        for (int it = 0; it < 96; it++) {
            float s = 0.f;
            #pragma unroll
            for (int j = 0; j < 32; j++)
                s += Ms[r*65 + part*32 + j] * va[part*32 + j];
            s += __shfl_xor_sync(0xffffffffu, s, 1);
            if (part == 0) vb[r] = ((it & 31) == 31) ? s * 1e-14f : s;
            __syncthreads();
            float* t = va; va = vb; vb = t;
        }
        {   // Rayleigh quotient
            float s = 0.f;
            #pragma unroll
            for (int j = 0; j < 32; j++)
                s += Ms[r*65 + part*32 + j] * va[part*32 + j];
            s += __shfl_xor_sync(0xffffffffu, s, 1);
            if (part == 0) vb[r] = s;
        }
        __syncthreads();
        if (tid == 0) {
            float num = 0.f, den = 0.f;
            for (int j = 0; j < 64; j++) { num += va[j]*vb[j]; den += va[j]*va[j]; }
            g_inv_sigma = 1.0f / sqrtf(num / den);
        }
        return;
    }

    // ---------------- GEMM block -----------------------------------------
    __nv_bfloat16* sAhi = sm;
    __nv_bfloat16* sAlo = sAhi + TILE_HALF;

    const int row0 = (blockIdx.x - 1) * GROWS;

    {   // stage x tile [64 rows][128 d] split hi/lo : 2048 float4, 16/thread
        const float4* xb = (const float4*)(x + (size_t)row0 * DDIM);
        #pragma unroll
        for (int i = 0; i < 16; i++) {
            int e = tid + 128 * i;
            int r = e >> 5, c4 = e & 31;       // 32 float4 per row
            float4 v = xb[e];
            __nv_bfloat16* dh = &sAhi[r * LDS_PAD + c4 * 4];
            __nv_bfloat16* dl = &sAlo[r * LDS_PAD + c4 * 4];
            float vv[4] = {v.x, v.y, v.z, v.w};
            #pragma unroll
            for (int q = 0; q < 4; q++) {
                __nv_bfloat16 h = __float2bfloat16(vv[q]);
                dh[q] = h;
                dl[q] = __float2bfloat16(vv[q] - __bfloat162float(h));
            }
        }
    }
    __syncthreads();

    // 4 warps: warp w covers rows w*16..w*16+15, all 64 cols (4 N-tiles)
    const int w = tid >> 5;
    wmma::fragment<wmma::accumulator, 16, 16, 16, float> fc[4];
    #pragma unroll
    for (int nt = 0; nt < 4; nt++) wmma::fill_fragment(fc[nt], 0.0f);

    wmma::fragment<wmma::matrix_a, 16, 16, 16, __nv_bfloat16, wmma::row_major> fa;
    wmma::fragment<wmma::matrix_b, 16, 16, 16, __nv_bfloat16, wmma::col_major> fb;

    const __nv_bfloat16* aSrc[3] = { sAhi, sAlo, sAhi };
    const __nv_bfloat16* bSrc[3] = { g_Whi, g_Whi, g_Wlo };

    #pragma unroll
    for (int p = 0; p < 3; p++) {
        const __nv_bfloat16* As = aSrc[p] + (w * 16) * LDS_PAD;
        const __nv_bfloat16* Bg = bSrc[p];
        #pragma unroll
        for (int kk = 0; kk < 8; kk++) {
            wmma::load_matrix_sync(fa, As + kk * 16, LDS_PAD);
            #pragma unroll
            for (int nt = 0; nt < 4; nt++) {
                // global, row-major [n][d] read as col_major k x n, ldm=128
                wmma::load_matrix_sync(fb, Bg + (nt * 16) * DDIM + kk * 16, DDIM);
                wmma::mma_sync(fc[nt], fa, fb, fc[nt]);
            }
        }
    }

    float* outp = &g_u[(size_t)(row0 + w * 16) * KDIM];
    #pragma unroll
    for (int nt = 0; nt < 4; nt++)
        wmma::store_matrix_sync(outp + nt * 16, fc[nt], KDIM, wmma::mem_row_major);
}

// =========================================================================
// Kernel 2: per-segment aggregates. Thread = (seg, k).
// Phase A: 16 independent coefficient computations (ILP); Phase B: chain.
// =========================================================================
__global__ __launch_bounds__(256) void aggregate_kernel(
    const float* __restrict__ dt,   const float* __restrict__ amod,
    const float* __restrict__ omod, const float* __restrict__ tmod,
    const float* __restrict__ srr,  const float* __restrict__ sim,
    const float* __restrict__ traw)
{
    const int tid = threadIdx.x;
    const int k   = tid & 63;
    const int seg = blockIdx.x * 4 + (tid >> 6);
    const int t0  = seg * SEGL;

    float tr  = traw[0];
    float tau = ((tr > 20.f) ? tr : log1pf(expf(tr))) + 1e-3f;
    float sr  = srr[k];
    float sp  = (sr > 20.f) ? sr : log1pf(expf(sr));
    float alpha0 = (sp + 1e-6f) * tau;
    float omega0 = sim[k] * tau;

    float cr[SEGL], ci[SEGL], uu[SEGL];
    #pragma unroll
    for (int i = 0; i < SEGL; i++) {
        int bt = t0 + i;
        size_t idx = (size_t)bt * KDIM + k;
        float tv  = tmod[bt];
        float dtv = dt[bt];
        float alpha = alpha0 * __expf(amod[idx] + tv);
        float omega = omega0 * __expf(omod[idx] + tv);
        float rho   = __expf(-alpha * dtv);
        float sn, cs; __sincosf(omega * dtv, &sn, &cs);
        cr[i] = rho * cs; ci[i] = rho * sn;
        uu[i] = g_u[idx];
    }

    float Ar = 1.f, Ai = 0.f, Br = 0.f, Bi = 0.f, Sr = 0.f, Si = 0.f;
    #pragma unroll
    for (int i = 0; i < SEGL; i++) {
        float car = cr[i], cai = ci[i];
        float nbr = car*Br - cai*Bi + uu[i];
        float nbi = car*Bi + cai*Br;
        float nsr = car*Sr - cai*Si + 1.f;
        float nsi = car*Si + cai*Sr;
        float nar = car*Ar - cai*Ai;
        float nai = car*Ai + cai*Ar;
        Br = nbr; Bi = nbi; Sr = nsr; Si = nsi; Ar = nar; Ai = nai;
    }
    g_segA[(size_t)seg * KDIM + k] = make_float4(Ar, Ai, Br, Bi);
    g_segS[(size_t)seg * KDIM + k] = make_float2(Sr, Si);
}

// =========================================================================
// Kernel 3: scan 512 segment aggregates per (batch,k); emit h_start.
// Grid 8 x 1024: 64 k x 16 groups of 32 segments.
// =========================================================================
__global__ __launch_bounds__(1024) void seg_scan_kernel(const float* __restrict__ bias)
{
    __shared__ float4 sAgg[16][KDIM];
    __shared__ float4 sPre[16][KDIM];

    const int tid = threadIdx.x;
    const int k   = tid & 63;
    const int grp = tid >> 6;       // 0..15
    const int b   = blockIdx.x;
    const float invsig = g_inv_sigma;
    const float bk = bias[k];

    const size_t base = ((size_t)b * 512 + grp * 32) * KDIM + k;

    float Ar = 1.f, Ai = 0.f, Br = 0.f, Bi = 0.f;
    #pragma unroll 8
    for (int s = 0; s < 32; s++) {
        float4 v = g_segA[base + (size_t)s * KDIM];
        float2 w = g_segS[base + (size_t)s * KDIM];
        float vBr = invsig * v.z + bk * w.x;
        float vBi = invsig * v.w + bk * w.y;
        float nAr = v.x*Ar - v.y*Ai;
        float nAi = v.x*Ai + v.y*Ar;
        float nBr = v.x*Br - v.y*Bi + vBr;
        float nBi = v.x*Bi + v.y*Br + vBi;
        Ar = nAr; Ai = nAi; Br = nBr; Bi = nBi;
    }
    sAgg[grp][k] = make_float4(Ar, Ai, Br, Bi);
    __syncthreads();

    if (tid < 64) {
        float EAr = 1.f, EAi = 0.f, EBr = 0.f, EBi = 0.f;
        #pragma unroll
        for (int g = 0; g < 16; g++) {
            sPre[g][k] = make_float4(EAr, EAi, EBr, EBi);
            float4 v = sAgg[g][k];
            float nAr = v.x*EAr - v.y*EAi;
            float nAi = v.x*EAi + v.y*EAr;
            float nBr = v.x*EBr - v.y*EBi + v.z;
            float nBi = v.x*EBi + v.y*EBr + v.w;
            EAr = nAr; EAi = nAi; EBr = nBr; EBi = nBi;
        }
    }
    __syncthreads();

    float4 E = sPre[grp][k];
    float EAr = E.x, EAi = E.y, EBr = E.z, EBi = E.w;
    #pragma unroll 8
    for (int s = 0; s < 32; s++) {
        g_hstart[base + (size_t)s * KDIM] = make_float2(EBr, EBi);
        float4 v = g_segA[base + (size_t)s * KDIM];
        float2 w = g_segS[base + (size_t)s * KDIM];
        float vBr = invsig * v.z + bk * w.x;
        float vBi = invsig * v.w + bk * w.y;
        float nAr = v.x*EAr - v.y*EAi;
        float nAi = v.x*EAi + v.y*EAr;
        float nBr = v.x*EBr - v.y*EBi + vBr;
        float nBi = v.x*EBi + v.y*EBr + vBi;
        EAr = nAr; EAi = nAi; EBr = nBr; EBi = nBi;
    }
}

// =========================================================================
// Kernel 4: apply pass. Thread = (segment, k). Precompute-then-chain.
// =========================================================================
__global__ __launch_bounds__(256) void apply_kernel(
    const float* __restrict__ dt,   const float* __restrict__ amod,
    const float* __restrict__ omod, const float* __restrict__ tmod,
    const float* __restrict__ srr,  const float* __restrict__ sim,
    const float* __restrict__ traw, const float* __restrict__ bias,
    float* __restrict__ out)
{
    const int tid = threadIdx.x;
    const int k   = tid & 63;
    const int seg = blockIdx.x * 4 + (tid >> 6);
    const int t0  = seg * SEGL;

    float tr  = traw[0];
    float tau = ((tr > 20.f) ? tr : log1pf(expf(tr))) + 1e-3f;
    float sr  = srr[k];
    float sp  = (sr > 20.f) ? sr : log1pf(expf(sr));
    float alpha0 = (sp + 1e-6f) * tau;
    float omega0 = sim[k] * tau;
    float bk     = bias[k];
    float invsig = g_inv_sigma;

    float cr[SEGL], ci[SEGL], uu[SEGL];
    #pragma unroll
    for (int i = 0; i < SEGL; i++) {
        int bt = t0 + i;
        size_t idx = (size_t)bt * KDIM + k;
        float tv  = tmod[bt];
        float dtv = dt[bt];
        float alpha = alpha0 * __expf(amod[idx] + tv);
        float omega = omega0 * __expf(omod[idx] + tv);
        float rho   = __expf(-alpha * dtv);
        float sn, cs; __sincosf(omega * dtv, &sn, &cs);
        cr[i] = rho * cs; ci[i] = rho * sn;
        uu[i] = g_u[idx] * invsig + bk;
    }

    float2 h = g_hstart[(size_t)seg * KDIM + k];
    float hr = h.x, hi = h.y;

    #pragma unroll
    for (int i = 0; i < SEGL; i++) {
        float nr = cr[i]*hr - ci[i]*hi + uu[i];
        float ni = cr[i]*hi + ci[i]*hr;
        hr = nr; hi = ni;
        size_t ob = (size_t)(t0 + i) * (2 * KDIM);
        out[ob + k]        = hr;   // C
        out[ob + KDIM + k] = hi;   // S
    }
}

// =========================================================================
extern "C" void kernel_launch(void* const* d_in, const int* in_sizes, int n_in,
                              void* d_out, int out_size)
{
    (void)in_sizes; (void)n_in; (void)out_size;
    const float* x    = (const float*)d_in[0];
    const float* dt   = (const float*)d_in[1];
    const float* amod = (const float*)d_in[2];
    const float* omod = (const float*)d_in[3];
    const float* tmod = (const float*)d_in[4];
    const float* srr  = (const float*)d_in[5];
    const float* sim  = (const float*)d_in[6];
    const float* traw = (const float*)d_in[7];
    const float* W    = (const float*)d_in[8];
    const float* bias = (const float*)d_in[9];
    float* out = (float*)d_out;

    prep_kernel<<<1, 128>>>(W);
    gemm_wmma_kernel<<<NGBLK + 1, 128>>>(x, W);
    aggregate_kernel<<<NSEG / 4, 256>>>(dt, amod, omod, tmod, srr, sim, traw);
    seg_scan_kernel<<<8, 1024>>>(bias);
    apply_kernel<<<NSEG / 4, 256>>>(dt, amod, omod, tmod, srr, sim, traw, bias, out);
}

// round 14
// speedup vs baseline: 1.6914x; 1.0826x over previous
#include <cuda_runtime.h>
#include <cuda_bf16.h>
#include <mma.h>
#include <cstdint>

using namespace nvcuda;

#define BDIM 8
#define TDIM 8192
#define KDIM 64
#define DDIM 128
#define SEGL 16
#define NSEG (BDIM * TDIM / SEGL)           // 4096 segments (16 steps each)
#define SUPL 16
#define NSUP (NSEG / SUPL)                  // 256 supersegments (256 steps)
#define SUP_PER_B (NSUP / BDIM)             // 32 per batch
#define GROWS 64
#define NGBLK (BDIM * TDIM / GROWS)         // 1024 gemm blocks

// ---------------- scratch (device globals; no allocation) ----------------
__device__ float  g_u[BDIM * TDIM * KDIM];        // raw x @ W^T
__device__ float4 g_segA[NSEG * KDIM];            // (Ar, Ai, Br, Bi)
__device__ float4 g_supA[NSUP * KDIM];            // superseg aggregates
__device__ float4 g_supPre[NSUP * KDIM];          // exclusive prefixes
__device__ float2 g_hstart[NSEG * KDIM];          // h at segment start
__device__ float  g_inv_sigma;
__device__ __nv_bfloat16 g_Whi[KDIM * DDIM];      // W split hi
__device__ __nv_bfloat16 g_Wlo[KDIM * DDIM];      // W split lo

#define LDS_PAD 136
#define TILE_HALF (GROWS * LDS_PAD)

// =========================================================================
// Kernel 0: split W -> bf16 hi/lo in global
// =========================================================================
__global__ __launch_bounds__(128) void prep_kernel(const float* __restrict__ W)
{
    const int tid = threadIdx.x;
    #pragma unroll
    for (int i = 0; i < KDIM * DDIM / 128; i++) {
        int e = tid + 128 * i;
        float v = W[e];
        __nv_bfloat16 h = __float2bfloat16(v);
        g_Whi[e] = h;
        g_Wlo[e] = __float2bfloat16(v - __bfloat162float(h));
    }
}

// =========================================================================
// Kernel 1: u = x@W^T (wmma bf16 split hi*hi + lo*hi + hi*lo) + sigma blk 0.
// A tile hi/lo in smem; B fragments direct from global (L1-resident).
// =========================================================================
__global__ __launch_bounds__(128)
void gemm_wmma_kernel(const float* __restrict__ x, const float* __restrict__ W)
{
    __shared__ __align__(16) __nv_bfloat16 sm[2 * TILE_HALF];   // 34816 B
    const int tid = threadIdx.x;

    if (blockIdx.x == 0) {
        // -------- sigma block: power iteration on W W^T (64x64) ----------
        float* Ms = (float*)sm;           // [64][65]
        float* v0 = Ms + 4160;
        float* v1 = v0 + 64;
        for (int e = tid; e < 4096; e += 128) {
            int r = e >> 6, c = e & 63;
            const float4* a = (const float4*)(W + r * DDIM);
            const float4* b = (const float4*)(W + c * DDIM);
            float s = 0.f;
            #pragma unroll
            for (int d = 0; d < 32; d++) {
                float4 av = a[d], bv = b[d];
                s += av.x*bv.x + av.y*bv.y + av.z*bv.z + av.w*bv.w;
            }
            Ms[r*65 + c] = s;
        }
        if (tid < 64) v0[tid] = 1.0f;
        __syncthreads();
        const int r = tid >> 1, part = tid & 1;
        float* va = v0; float* vb = v1;
        for (int it = 0; it < 96; it++) {
            float s = 0.f;
            #pragma unroll
            for (int j = 0; j < 32; j++)
                s += Ms[r*65 + part*32 + j] * va[part*32 + j];
            s += __shfl_xor_sync(0xffffffffu, s, 1);
            if (part == 0) vb[r] = ((it & 31) == 31) ? s * 1e-14f : s;
            __syncthreads();
            float* t = va; va = vb; vb = t;
        }
        {   // Rayleigh quotient
            float s = 0.f;
            #pragma unroll
            for (int j = 0; j < 32; j++)
                s += Ms[r*65 + part*32 + j] * va[part*32 + j];
            s += __shfl_xor_sync(0xffffffffu, s, 1);
            if (part == 0) vb[r] = s;
        }
        __syncthreads();
        if (tid == 0) {
            float num = 0.f, den = 0.f;
            for (int j = 0; j < 64; j++) { num += va[j]*vb[j]; den += va[j]*va[j]; }
            g_inv_sigma = 1.0f / sqrtf(num / den);
        }
        return;
    }

    // ---------------- GEMM block -----------------------------------------
    __nv_bfloat16* sAhi = sm;
    __nv_bfloat16* sAlo = sAhi + TILE_HALF;

    const int row0 = (blockIdx.x - 1) * GROWS;

    {   // stage x tile [64 rows][128 d] split hi/lo
        const float4* xb = (const float4*)(x + (size_t)row0 * DDIM);
        #pragma unroll
        for (int i = 0; i < 16; i++) {
            int e = tid + 128 * i;
            int r = e >> 5, c4 = e & 31;
            float4 v = xb[e];
            __nv_bfloat16* dh = &sAhi[r * LDS_PAD + c4 * 4];
            __nv_bfloat16* dl = &sAlo[r * LDS_PAD + c4 * 4];
            float vv[4] = {v.x, v.y, v.z, v.w};
            #pragma unroll
            for (int q = 0; q < 4; q++) {
                __nv_bfloat16 h = __float2bfloat16(vv[q]);
                dh[q] = h;
                dl[q] = __float2bfloat16(vv[q] - __bfloat162float(h));
            }
        }
    }
    __syncthreads();

    const int w = tid >> 5;
    wmma::fragment<wmma::accumulator, 16, 16, 16, float> fc[4];
    #pragma unroll
    for (int nt = 0; nt < 4; nt++) wmma::fill_fragment(fc[nt], 0.0f);

    wmma::fragment<wmma::matrix_a, 16, 16, 16, __nv_bfloat16, wmma::row_major> fahi, falo;
    wmma::fragment<wmma::matrix_b, 16, 16, 16, __nv_bfloat16, wmma::col_major> fbhi, fblo;

    const __nv_bfloat16* As = sAhi + (w * 16) * LDS_PAD;
    const __nv_bfloat16* Al = sAlo + (w * 16) * LDS_PAD;

    #pragma unroll
    for (int kk = 0; kk < 8; kk++) {
        wmma::load_matrix_sync(fahi, As + kk * 16, LDS_PAD);
        wmma::load_matrix_sync(falo, Al + kk * 16, LDS_PAD);
        #pragma unroll
        for (int nt = 0; nt < 4; nt++) {
            wmma::load_matrix_sync(fbhi, g_Whi + (nt * 16) * DDIM + kk * 16, DDIM);
            wmma::mma_sync(fc[nt], fahi, fbhi, fc[nt]);   // hi*hi
            wmma::mma_sync(fc[nt], falo, fbhi, fc[nt]);   // lo*hi
            wmma::load_matrix_sync(fblo, g_Wlo + (nt * 16) * DDIM + kk * 16, DDIM);
            wmma::mma_sync(fc[nt], fahi, fblo, fc[nt]);   // hi*lo
        }
    }

    float* outp = &g_u[(size_t)(row0 + w * 16) * KDIM];
    #pragma unroll
    for (int nt = 0; nt < 4; nt++)
        wmma::store_matrix_sync(outp + nt * 16, fc[nt], KDIM, wmma::mem_row_major);
}

// =========================================================================
// Kernel 2: per-segment aggregates, sigma+bias folded in. Grid 1024 x 256.
// =========================================================================
__global__ __launch_bounds__(256) void aggregate_kernel(
    const float* __restrict__ dt,   const float* __restrict__ amod,
    const float* __restrict__ omod, const float* __restrict__ tmod,
    const float* __restrict__ srr,  const float* __restrict__ sim,
    const float* __restrict__ traw, const float* __restrict__ bias)
{
    const int tid = threadIdx.x;
    const int k   = tid & 63;
    const int seg = blockIdx.x * 4 + (tid >> 6);
    const int t0  = seg * SEGL;

    float tr  = traw[0];
    float tau = ((tr > 20.f) ? tr : log1pf(expf(tr))) + 1e-3f;
    float sr  = srr[k];
    float sp  = (sr > 20.f) ? sr : log1pf(expf(sr));
    float alpha0 = (sp + 1e-6f) * tau;
    float omega0 = sim[k] * tau;
    float bk     = bias[k];
    float invsig = g_inv_sigma;

    float cr[SEGL], ci[SEGL], uu[SEGL];
    #pragma unroll
    for (int i = 0; i < SEGL; i++) {
        int bt = t0 + i;
        size_t idx = (size_t)bt * KDIM + k;
        float tv  = tmod[bt];
        float dtv = dt[bt];
        float alpha = alpha0 * __expf(amod[idx] + tv);
        float omega = omega0 * __expf(omod[idx] + tv);
        float rho   = __expf(-alpha * dtv);
        float sn, cs; __sincosf(omega * dtv, &sn, &cs);
        cr[i] = rho * cs; ci[i] = rho * sn;
        uu[i] = g_u[idx] * invsig + bk;
    }

    float Ar = 1.f, Ai = 0.f, Br = 0.f, Bi = 0.f;
    #pragma unroll
    for (int i = 0; i < SEGL; i++) {
        float car = cr[i], cai = ci[i];
        float nbr = car*Br - cai*Bi + uu[i];
        float nbi = car*Bi + cai*Br;
        float nar = car*Ar - cai*Ai;
        float nai = car*Ai + cai*Ar;
        Br = nbr; Bi = nbi; Ar = nar; Ai = nai;
    }
    g_segA[(size_t)seg * KDIM + k] = make_float4(Ar, Ai, Br, Bi);
}

// =========================================================================
// Kernel 3a: superseg aggregates (combine 16 segAs). Grid 64 x 256.
// =========================================================================
__global__ __launch_bounds__(256) void superagg_kernel()
{
    const int tid = threadIdx.x;
    const int k   = tid & 63;
    const int sup = blockIdx.x * 4 + (tid >> 6);
    const size_t base = (size_t)sup * SUPL * KDIM + k;

    float4 v[SUPL];
    #pragma unroll
    for (int j = 0; j < SUPL; j++) v[j] = g_segA[base + (size_t)j * KDIM];

    float Ar = 1.f, Ai = 0.f, Br = 0.f, Bi = 0.f;
    #pragma unroll
    for (int j = 0; j < SUPL; j++) {
        float nAr = v[j].x*Ar - v[j].y*Ai;
        float nAi = v[j].x*Ai + v[j].y*Ar;
        float nBr = v[j].x*Br - v[j].y*Bi + v[j].z;
        float nBi = v[j].x*Bi + v[j].y*Br + v[j].w;
        Ar = nAr; Ai = nAi; Br = nBr; Bi = nBi;
    }
    g_supA[(size_t)sup * KDIM + k] = make_float4(Ar, Ai, Br, Bi);
}

// =========================================================================
// Kernel 3b: exclusive scan of 32 supersegs per (batch, k). Grid 8 x 64.
// Two register batches of 16 (keeps prefetch in-register, no spill).
// =========================================================================
__global__ __launch_bounds__(64) void topscan_kernel()
{
    const int k = threadIdx.x;
    const int b = blockIdx.x;
    const size_t base = (size_t)b * SUP_PER_B * KDIM + k;

    float EAr = 1.f, EAi = 0.f, EBr = 0.f, EBi = 0.f;
    #pragma unroll
    for (int half = 0; half < 2; half++) {
        float4 v[16];
        #pragma unroll
        for (int j = 0; j < 16; j++)
            v[j] = g_supA[base + (size_t)(half * 16 + j) * KDIM];
        #pragma unroll
        for (int j = 0; j < 16; j++) {
            g_supPre[base + (size_t)(half * 16 + j) * KDIM] =
                make_float4(EAr, EAi, EBr, EBi);
            float nAr = v[j].x*EAr - v[j].y*EAi;
            float nAi = v[j].x*EAi + v[j].y*EAr;
            float nBr = v[j].x*EBr - v[j].y*EBi + v[j].z;
            float nBi = v[j].x*EBi + v[j].y*EBr + v[j].w;
            EAr = nAr; EAi = nAi; EBr = nBr; EBi = nBi;
        }
    }
}

// =========================================================================
// Kernel 3c: expand superseg prefixes to per-segment h_start. Grid 64 x 256.
// =========================================================================
__global__ __launch_bounds__(256) void hstart_kernel()
{
    const int tid = threadIdx.x;
    const int k   = tid & 63;
    const int sup = blockIdx.x * 4 + (tid >> 6);
    const size_t base = (size_t)sup * SUPL * KDIM + k;

    float4 v[SUPL];
    #pragma unroll
    for (int j = 0; j < SUPL; j++) v[j] = g_segA[base + (size_t)j * KDIM];

    float4 E = g_supPre[(size_t)sup * KDIM + k];
    float EAr = E.x, EAi = E.y, EBr = E.z, EBi = E.w;
    #pragma unroll
    for (int j = 0; j < SUPL; j++) {
        g_hstart[base + (size_t)j * KDIM] = make_float2(EBr, EBi);   // h0 = 0
        float nAr = v[j].x*EAr - v[j].y*EAi;
        float nAi = v[j].x*EAi + v[j].y*EAr;
        float nBr = v[j].x*EBr - v[j].y*EBi + v[j].z;
        float nBi = v[j].x*EBi + v[j].y*EBr + v[j].w;
        EAr = nAr; EAi = nAi; EBr = nBr; EBi = nBi;
    }
}

// =========================================================================
// Kernel 4: apply pass. Thread = (segment, k). Prefetch-then-chain.
// =========================================================================
__global__ __launch_bounds__(256) void apply_kernel(
    const float* __restrict__ dt,   const float* __restrict__ amod,
    const float* __restrict__ omod, const float* __restrict__ tmod,
    const float* __restrict__ srr,  const float* __restrict__ sim,
    const float* __restrict__ traw, const float* __restrict__ bias,
    float* __restrict__ out)
{
    const int tid = threadIdx.x;
    const int k   = tid & 63;
    const int seg = blockIdx.x * 4 + (tid >> 6);
    const int t0  = seg * SEGL;

    float tr  = traw[0];
    float tau = ((tr > 20.f) ? tr : log1pf(expf(tr))) + 1e-3f;
    float sr  = srr[k];
    float sp  = (sr > 20.f) ? sr : log1pf(expf(sr));
    float alpha0 = (sp + 1e-6f) * tau;
    float omega0 = sim[k] * tau;
    float bk     = bias[k];
    float invsig = g_inv_sigma;

    float cr[SEGL], ci[SEGL], uu[SEGL];
    #pragma unroll
    for (int i = 0; i < SEGL; i++) {
        int bt = t0 + i;
        size_t idx = (size_t)bt * KDIM + k;
        float tv  = tmod[bt];
        float dtv = dt[bt];
        float alpha = alpha0 * __expf(amod[idx] + tv);
        float omega = omega0 * __expf(omod[idx] + tv);
        float rho   = __expf(-alpha * dtv);
        float sn, cs; __sincosf(omega * dtv, &sn, &cs);
        cr[i] = rho * cs; ci[i] = rho * sn;
        uu[i] = g_u[idx] * invsig + bk;
    }

    float2 h = g_hstart[(size_t)seg * KDIM + k];
    float hr = h.x, hi = h.y;

    #pragma unroll
    for (int i = 0; i < SEGL; i++) {
        float nr = cr[i]*hr - ci[i]*hi + uu[i];
        float ni = cr[i]*hi + ci[i]*hr;
        hr = nr; hi = ni;
        size_t ob = (size_t)(t0 + i) * (2 * KDIM);
        out[ob + k]        = hr;   // C
        out[ob + KDIM + k] = hi;   // S
    }
}

// =========================================================================
extern "C" void kernel_launch(void* const* d_in, const int* in_sizes, int n_in,
                              void* d_out, int out_size)
{
    (void)in_sizes; (void)n_in; (void)out_size;
    const float* x    = (const float*)d_in[0];
    const float* dt   = (const float*)d_in[1];
    const float* amod = (const float*)d_in[2];
    const float* omod = (const float*)d_in[3];
    const float* tmod = (const float*)d_in[4];
    const float* srr  = (const float*)d_in[5];
    const float* sim  = (const float*)d_in[6];
    const float* traw = (const float*)d_in[7];
    const float* W    = (const float*)d_in[8];
    const float* bias = (const float*)d_in[9];
    float* out = (float*)d_out;

    prep_kernel<<<1, 128>>>(W);
    gemm_wmma_kernel<<<NGBLK + 1, 128>>>(x, W);
    aggregate_kernel<<<NSEG / 4, 256>>>(dt, amod, omod, tmod, srr, sim, traw, bias);
    superagg_kernel<<<NSUP / 4, 256>>>();
    topscan_kernel<<<BDIM, 64>>>();
    hstart_kernel<<<NSUP / 4, 256>>>();
    apply_kernel<<<NSEG / 4, 256>>>(dt, amod, omod, tmod, srr, sim, traw, bias, out);
}